// round 2
// baseline (speedup 1.0000x reference)
#include <cuda_runtime.h>
#include <math.h>

// Problem constants (SUBDIVISIONS=7, BATCH=16)
#define BATCH    16
#define NV       163842        // total vertices (grid + 2 poles)
#define YXN      163840        // grid vertices (Y=640, X=256)
#define XDIM     256
#define NFACE    327680        // faces
#define NDIR     983040        // directed edges == 3*NFACE == sum(deg)

// Scratch (static __device__ allocations are allowed; cudaMalloc is not)
__device__ float4 g_v[(size_t)BATCH * NV];   // positions, w=0  (~42 MB)
__device__ int    g_off[NV + 1];             // CSR offsets (edges AND faces share them)
__device__ int    g_cursor[NV];              // CSR fill cursors
__device__ int    g_face_csr[NDIR];          // vertex -> incident face ids
__device__ double g_acc;                     // loss accumulator

// ---------------------------------------------------------------------------
// K0: derive CSR offsets from sorted edge_src (boundary scatter), zero cursors
// ---------------------------------------------------------------------------
__global__ void k_prep(const int* __restrict__ esrc) {
    int t = blockIdx.x * blockDim.x + threadIdx.x;
    if (t < NDIR) {
        int s = __ldg(&esrc[t]);
        if (t == 0) {
            g_off[s] = 0;
        } else {
            int p = __ldg(&esrc[t - 1]);
            if (p != s) g_off[s] = t;
        }
    }
    if (t < NV) g_cursor[t] = 0;
    if (t == 0) { g_acc = 0.0; g_off[NV] = NDIR; }
}

// ---------------------------------------------------------------------------
// K1: build v as float4 per (batch, vertex); poles = mean of 5 grid samples
// ---------------------------------------------------------------------------
__global__ void k_build_v(const float* __restrict__ inp) {
    int i = blockIdx.x * blockDim.x + threadIdx.x;
    int b = blockIdx.y;
    if (i >= NV) return;
    const float* base = inp + (size_t)b * 3 * YXN;
    float x, y, z;
    if (i < YXN) {
        x = __ldg(&base[i]);
        y = __ldg(&base[YXN + i]);
        z = __ldg(&base[2 * YXN + i]);
    } else {
        // top pole (i==YXN): rows {0,128,...,512}, col 0
        // bot pole (i==YXN+1): rows {127,255,...,639}, col 255
        bool top = (i == YXN);
        float sx = 0.f, sy = 0.f, sz = 0.f;
#pragma unroll
        for (int r = 0; r < 5; r++) {
            int idx = top ? (r * 128 * XDIM)
                          : ((r * 128 + 127) * XDIM + (XDIM - 1));
            sx += __ldg(&base[idx]);
            sy += __ldg(&base[YXN + idx]);
            sz += __ldg(&base[2 * YXN + idx]);
        }
        x = sx * 0.2f; y = sy * 0.2f; z = sz * 0.2f;
    }
    g_v[(size_t)b * NV + i] = make_float4(x, y, z, 0.f);
}

// ---------------------------------------------------------------------------
// K2: fill vertex->face CSR (closed manifold: face-degree == edge-degree)
// ---------------------------------------------------------------------------
__global__ void k_csr(const int* __restrict__ faces) {
    int f = blockIdx.x * blockDim.x + threadIdx.x;
    if (f >= NFACE) return;
    int a = __ldg(&faces[3 * f]);
    int b = __ldg(&faces[3 * f + 1]);
    int c = __ldg(&faces[3 * f + 2]);
    int pa = atomicAdd(&g_cursor[a], 1); g_face_csr[g_off[a] + pa] = f;
    int pb = atomicAdd(&g_cursor[b], 1); g_face_csr[g_off[b] + pb] = f;
    int pc = atomicAdd(&g_cursor[c], 1); g_face_csr[g_off[c] + pc] = f;
}

// ---------------------------------------------------------------------------
// K3: fused loss — per (batch, vertex): pos SSE, laplacian SSE, 1-cos(vn,tn)
// ---------------------------------------------------------------------------
__global__ void __launch_bounds__(256)
k_main(const float* __restrict__ target,
       const int*   __restrict__ faces,
       const int*   __restrict__ edst,
       const float* __restrict__ degree) {
    int i = blockIdx.x * blockDim.x + threadIdx.x;
    int b = blockIdx.y;

    float contrib = 0.f;
    if (i < NV) {
        const float4* __restrict__ vb = g_v + (size_t)b * NV;
        float4 vi = vb[i];

        int s   = g_off[i];
        int cnt = g_off[i + 1] - s;   // 5 or 6

        // Neighbor sum (gather version of the edge scatter)
        float nx = 0.f, ny = 0.f, nz = 0.f;
#pragma unroll
        for (int t = 0; t < 6; t++) {
            if (t < cnt) {
                int j = __ldg(&edst[s + t]);
                float4 vj = vb[j];
                nx += vj.x; ny += vj.y; nz += vj.z;
            }
        }

        // Vertex normal = sum of incident face normals (gather via face CSR),
        // exact reference formula cross(v1-v0, v2-v0)
        float vnx = 0.f, vny = 0.f, vnz = 0.f;
#pragma unroll
        for (int t = 0; t < 6; t++) {
            if (t < cnt) {
                int f  = g_face_csr[s + t];
                int a0 = __ldg(&faces[3 * f]);
                int a1 = __ldg(&faces[3 * f + 1]);
                int a2 = __ldg(&faces[3 * f + 2]);
                float4 p0 = vb[a0];
                float4 p1 = vb[a1];
                float4 p2 = vb[a2];
                float e1x = p1.x - p0.x, e1y = p1.y - p0.y, e1z = p1.z - p0.z;
                float e2x = p2.x - p0.x, e2y = p2.y - p0.y, e2z = p2.z - p0.z;
                vnx += e1y * e2z - e1z * e2y;
                vny += e1z * e2x - e1x * e2z;
                vnz += e1x * e2y - e1y * e2x;
            }
        }

        float dg  = __ldg(&degree[i]);
        float idg = 1.0f / dg;
        float lx = vi.x - nx * idg;
        float ly = vi.y - ny * idg;
        float lz = vi.z - nz * idg;

        const float* __restrict__ tb = target + (size_t)b * 9 * NV;
        float tvx = __ldg(&tb[0 * NV + i]);
        float tvy = __ldg(&tb[1 * NV + i]);
        float tvz = __ldg(&tb[2 * NV + i]);
        float tnx = __ldg(&tb[3 * NV + i]);
        float tny = __ldg(&tb[4 * NV + i]);
        float tnz = __ldg(&tb[5 * NV + i]);
        float tlx = __ldg(&tb[6 * NV + i]);
        float tly = __ldg(&tb[7 * NV + i]);
        float tlz = __ldg(&tb[8 * NV + i]);

        float dpx = vi.x - tvx, dpy = vi.y - tvy, dpz = vi.z - tvz;
        float pos_sse = dpx * dpx + dpy * dpy + dpz * dpz;

        float dlx = lx - tlx, dly = ly - tly, dlz = lz - tlz;
        float lap_sse = dlx * dlx + dly * dly + dlz * dlz;

        // cosine term, replicating the reference's epsilon chain
        float nrm   = sqrtf(vnx * vnx + vny * vny + vnz * vnz);
        float inv_n = 1.0f / fmaxf(nrm, 1e-12f);
        float hx = vnx * inv_n, hy = vny * inv_n, hz = vnz * inv_n;
        float hn   = sqrtf(hx * hx + hy * hy + hz * hz);
        float tnn  = sqrtf(tnx * tnx + tny * tny + tnz * tnz);
        float cosv = (hx * tnx + hy * tny + hz * tnz) / fmaxf(hn * tnn, 1e-8f);

        const float invP = 1.0f / ((float)BATCH * (float)NV * 3.0f);
        const float invN = 1.0f / ((float)BATCH * (float)NV);
        contrib = (pos_sse + lap_sse) * invP + (1.0f - cosv) * invN;
    }

    // Block reduction (all threads participate; tail threads contribute 0)
#pragma unroll
    for (int o = 16; o > 0; o >>= 1)
        contrib += __shfl_down_sync(0xffffffff, contrib, o);

    __shared__ float ws[8];
    int lane = threadIdx.x & 31;
    int w    = threadIdx.x >> 5;
    if (lane == 0) ws[w] = contrib;
    __syncthreads();
    if (w == 0) {
        float v = (lane < 8) ? ws[lane] : 0.f;
#pragma unroll
        for (int o = 4; o > 0; o >>= 1)
            v += __shfl_down_sync(0xff, v, o);
        if (lane == 0) atomicAdd(&g_acc, (double)v);
    }
}

// ---------------------------------------------------------------------------
// K4: write scalar result
// ---------------------------------------------------------------------------
__global__ void k_final(float* __restrict__ out) {
    out[0] = (float)g_acc;
}

// ---------------------------------------------------------------------------
// Launch: inputs order = inputs, target, ico_faces, edge_src, edge_dst, degree
// ---------------------------------------------------------------------------
extern "C" void kernel_launch(void* const* d_in, const int* in_sizes, int n_in,
                              void* d_out, int out_size) {
    const float* inputs = (const float*)d_in[0];
    const float* target = (const float*)d_in[1];
    const int*   faces  = (const int*)  d_in[2];
    const int*   esrc   = (const int*)  d_in[3];
    const int*   edst   = (const int*)  d_in[4];
    const float* degree = (const float*)d_in[5];

    const int TB = 256;

    k_prep<<<(NDIR + TB - 1) / TB, TB>>>(esrc);

    dim3 gv((NV + TB - 1) / TB, BATCH);
    k_build_v<<<gv, TB>>>(inputs);

    k_csr<<<(NFACE + TB - 1) / TB, TB>>>(faces);

    dim3 gm((NV + TB - 1) / TB, BATCH);
    k_main<<<gm, TB>>>(target, faces, edst, degree);

    k_final<<<1, 1>>>((float*)d_out);
}

// round 3
// speedup vs baseline: 2.4299x; 2.4299x over previous
#include <cuda_runtime.h>
#include <math.h>

// Problem constants (SUBDIVISIONS=7, BATCH=16)
#define BATCH    16
#define NV       163842        // total vertices (grid + 2 poles)
#define YXN      163840        // grid vertices (Y=640, X=256)
#define XDIM     256
#define NFACE    327680
#define NDIR     983040        // directed edges == 3*NFACE == sum(deg)
#define VPB      16            // vertices per block in transposed kernels

// Scratch (__device__ globals; no runtime allocation)
__device__ float4 g_vT[(size_t)NV * BATCH];  // positions, [vertex][batch], w=0
__device__ int    g_off[NV + 1];             // CSR offsets (edge-degree == face-degree)
__device__ int    g_cursor[NV];
__device__ int2   g_pairs[NDIR];             // per vertex slot: opposite edge (p,q), cyclic
__device__ int    g_ring[NDIR];              // ring-ordered neighbor ids per vertex
__device__ double g_acc;

// ---------------------------------------------------------------------------
// K0: CSR offsets from sorted edge_src; zero cursors + accumulator
// ---------------------------------------------------------------------------
__global__ void k_prep(const int* __restrict__ esrc) {
    int t = blockIdx.x * blockDim.x + threadIdx.x;
    if (t < NDIR) {
        int s = __ldg(&esrc[t]);
        if (t == 0) g_off[s] = 0;
        else if (__ldg(&esrc[t - 1]) != s) g_off[s] = t;
    }
    if (t < NV) g_cursor[t] = 0;
    if (t == 0) { g_acc = 0.0; g_off[NV] = NDIR; }
}

// ---------------------------------------------------------------------------
// K1: per face (a,b,c), deposit the opposite edge in cyclic order at each corner
// ---------------------------------------------------------------------------
__global__ void k_pairs(const int* __restrict__ faces) {
    int f = blockIdx.x * blockDim.x + threadIdx.x;
    if (f >= NFACE) return;
    int a = __ldg(&faces[3 * f]);
    int b = __ldg(&faces[3 * f + 1]);
    int c = __ldg(&faces[3 * f + 2]);
    int pa = atomicAdd(&g_cursor[a], 1); g_pairs[g_off[a] + pa] = make_int2(b, c);
    int pb = atomicAdd(&g_cursor[b], 1); g_pairs[g_off[b] + pb] = make_int2(c, a);
    int pc = atomicAdd(&g_cursor[c], 1); g_pairs[g_off[c] + pc] = make_int2(a, b);
}

// ---------------------------------------------------------------------------
// K2: chain the (p,q) pairs into a deterministic ring order per vertex.
// Start at the pair with the minimal p so output is order-independent.
// ---------------------------------------------------------------------------
__global__ void k_ring(void) {
    int i = blockIdx.x * blockDim.x + threadIdx.x;
    if (i >= NV) return;
    int s   = g_off[i];
    int cnt = g_off[i + 1] - s;      // 5 or 6
    int p[6], q[6];
#pragma unroll
    for (int k = 0; k < 6; k++) {
        int2 pr = (k < cnt) ? g_pairs[s + k] : make_int2(0x7fffffff, 0x7fffffff);
        p[k] = pr.x; q[k] = pr.y;
    }
    // start at min p (deterministic)
    int cur = 0x7fffffff, nxt = 0;
#pragma unroll
    for (int k = 0; k < 6; k++) if (p[k] < cur) { cur = p[k]; nxt = q[k]; }
    g_ring[s] = cur;
    cur = nxt;
    for (int t = 1; t < cnt; t++) {
        g_ring[s + t] = cur;
        int nq = cur;
#pragma unroll
        for (int k = 0; k < 6; k++) if (p[k] == cur) nq = q[k];
        cur = nq;
    }
}

// ---------------------------------------------------------------------------
// K3: build transposed positions g_vT[vertex][batch] with smem transpose.
// Block = 16 grid-vertices x 16 batches.
// ---------------------------------------------------------------------------
__global__ void __launch_bounds__(256) k_build_v(const float* __restrict__ inp) {
    __shared__ float st[3][VPB][BATCH + 1];
    int tid = threadIdx.x;
    int hv  = tid >> 4;          // loader: batch row   | compute: local vertex
    int lo  = tid & 15;          // loader: vertex col  | compute: batch
    int i0  = blockIdx.x * VPB;
    // Coalesced stage: lanes 0..15 read consecutive i for fixed (b,c)
    {
        size_t base = (size_t)hv * 3 * YXN + (size_t)(i0 + lo);
#pragma unroll
        for (int c = 0; c < 3; c++)
            st[c][lo][hv] = __ldg(&inp[base + (size_t)c * YXN]);
    }
    __syncthreads();
    // Coalesced transposed write: tid-ordered consecutive float4
    g_vT[(size_t)(i0 + hv) * BATCH + lo] =
        make_float4(st[0][hv][lo], st[1][hv][lo], st[2][hv][lo], 0.f);
}

// K3b: the two poles (mean of 5 grid samples each), 2 poles x 16 batches
__global__ void k_poles(const float* __restrict__ inp) {
    int tid  = threadIdx.x;
    if (tid >= 32) return;
    int b    = tid & 15;
    int pole = tid >> 4;                  // 0 = top, 1 = bottom
    const float* base = inp + (size_t)b * 3 * YXN;
    float sx = 0.f, sy = 0.f, sz = 0.f;
#pragma unroll
    for (int r = 0; r < 5; r++) {
        int idx = pole ? ((r * 128 + 127) * XDIM + (XDIM - 1))
                       : (r * 128 * XDIM);
        sx += __ldg(&base[idx]);
        sy += __ldg(&base[YXN + idx]);
        sz += __ldg(&base[2 * YXN + idx]);
    }
    g_vT[(size_t)(YXN + pole) * BATCH + b] =
        make_float4(sx * 0.2f, sy * 0.2f, sz * 0.2f, 0.f);
}

// ---------------------------------------------------------------------------
// K4: fused loss. Block = 16 vertices x 16 batches; half-warp = 1 vertex.
// vn_i = sum over ring edges of cross(v_t, v_{t+1})  (exact identity with the
// reference's sum of cross(v1-v0, v2-v0) over incident faces).
// ---------------------------------------------------------------------------
__global__ void __launch_bounds__(256)
k_main(const float* __restrict__ target) {
    __shared__ float st[9][VPB][BATCH + 1];
    int tid = threadIdx.x;
    int hv  = tid >> 4;      // loader batch / compute local-vertex
    int lo  = tid & 15;      // loader vertex / compute batch
    int i0  = blockIdx.x * VPB;

    // Stage target tile (coalesced 64B segments)
    {
        int gi = i0 + lo;
        size_t base = (size_t)hv * 9 * NV + (size_t)gi;
#pragma unroll
        for (int c = 0; c < 9; c++)
            st[c][lo][hv] = (gi < NV) ? __ldg(&target[base + (size_t)c * NV]) : 0.f;
    }
    __syncthreads();

    int i = i0 + hv;
    int b = lo;
    float contrib = 0.f;

    if (i < NV) {
        int s   = __ldg(&g_off[i]);
        int cnt = __ldg(&g_off[i + 1]) - s;    // 5 or 6 (uniform per half-warp)

        float4 vi = g_vT[(size_t)i * BATCH + b];

        // Ring neighbor ids (uniform across the half-warp -> broadcast loads)
        int idx[6];
#pragma unroll
        for (int t = 0; t < 6; t++)
            idx[t] = (t < cnt) ? __ldg(&g_ring[s + t]) : 0;

        // Gather neighbor positions: 16 consecutive float4 per half-warp
        float4 nb[6];
#pragma unroll
        for (int t = 0; t < 6; t++)
            nb[t] = g_vT[(size_t)idx[t] * BATCH + b];

        // Neighbor sum (Laplacian) over the ring set
        float nx = 0.f, ny = 0.f, nz = 0.f;
#pragma unroll
        for (int t = 0; t < 6; t++)
            if (t < cnt) { nx += nb[t].x; ny += nb[t].y; nz += nb[t].z; }

        // Vertex normal: sum of cross over consecutive ring pairs + wrap
        float vnx = 0.f, vny = 0.f, vnz = 0.f;
#pragma unroll
        for (int t = 0; t < 5; t++) {
            if (t + 1 < cnt) {
                vnx += nb[t].y * nb[t + 1].z - nb[t].z * nb[t + 1].y;
                vny += nb[t].z * nb[t + 1].x - nb[t].x * nb[t + 1].z;
                vnz += nb[t].x * nb[t + 1].y - nb[t].y * nb[t + 1].x;
            }
        }
        float4 last = (cnt == 6) ? nb[5] : nb[4];
        vnx += last.y * nb[0].z - last.z * nb[0].y;
        vny += last.z * nb[0].x - last.x * nb[0].z;
        vnz += last.x * nb[0].y - last.y * nb[0].x;

        float idg = 1.0f / (float)cnt;
        float lx = vi.x - nx * idg;
        float ly = vi.y - ny * idg;
        float lz = vi.z - nz * idg;

        float tvx = st[0][hv][b], tvy = st[1][hv][b], tvz = st[2][hv][b];
        float tnx = st[3][hv][b], tny = st[4][hv][b], tnz = st[5][hv][b];
        float tlx = st[6][hv][b], tly = st[7][hv][b], tlz = st[8][hv][b];

        float dpx = vi.x - tvx, dpy = vi.y - tvy, dpz = vi.z - tvz;
        float pos_sse = dpx * dpx + dpy * dpy + dpz * dpz;

        float dlx = lx - tlx, dly = ly - tly, dlz = lz - tlz;
        float lap_sse = dlx * dlx + dly * dly + dlz * dlz;

        // cosine, replicating the reference's epsilon chain
        float nrm   = sqrtf(vnx * vnx + vny * vny + vnz * vnz);
        float inv_n = 1.0f / fmaxf(nrm, 1e-12f);
        float hx = vnx * inv_n, hy = vny * inv_n, hz = vnz * inv_n;
        float hn  = sqrtf(hx * hx + hy * hy + hz * hz);
        float tnn = sqrtf(tnx * tnx + tny * tny + tnz * tnz);
        float cosv = (hx * tnx + hy * tny + hz * tnz) / fmaxf(hn * tnn, 1e-8f);

        const float invP = 1.0f / ((float)BATCH * (float)NV * 3.0f);
        const float invN = 1.0f / ((float)BATCH * (float)NV);
        contrib = (pos_sse + lap_sse) * invP + (1.0f - cosv) * invN;
    }

    // Block reduce -> one double atomic per block
#pragma unroll
    for (int o = 16; o > 0; o >>= 1)
        contrib += __shfl_down_sync(0xffffffff, contrib, o);

    __shared__ float ws[8];
    int lane = threadIdx.x & 31;
    int w    = threadIdx.x >> 5;
    if (lane == 0) ws[w] = contrib;
    __syncthreads();
    if (w == 0) {
        float v = (lane < 8) ? ws[lane] : 0.f;
#pragma unroll
        for (int o = 4; o > 0; o >>= 1)
            v += __shfl_down_sync(0xff, v, o);
        if (lane == 0) atomicAdd(&g_acc, (double)v);
    }
}

__global__ void k_final(float* __restrict__ out) {
    out[0] = (float)g_acc;
}

// ---------------------------------------------------------------------------
// inputs order: inputs, target, ico_faces, edge_src, edge_dst, degree
// ---------------------------------------------------------------------------
extern "C" void kernel_launch(void* const* d_in, const int* in_sizes, int n_in,
                              void* d_out, int out_size) {
    const float* inputs = (const float*)d_in[0];
    const float* target = (const float*)d_in[1];
    const int*   faces  = (const int*)  d_in[2];
    const int*   esrc   = (const int*)  d_in[3];

    const int TB = 256;

    k_prep <<<(NDIR + TB - 1) / TB, TB>>>(esrc);
    k_pairs<<<(NFACE + TB - 1) / TB, TB>>>(faces);
    k_ring <<<(NV + TB - 1) / TB, TB>>>();

    k_build_v<<<YXN / VPB, TB>>>(inputs);
    k_poles  <<<1, 32>>>(inputs);

    k_main<<<(NV + VPB - 1) / VPB, TB>>>(target);
    k_final<<<1, 1>>>((float*)d_out);
}

// round 4
// speedup vs baseline: 2.4417x; 1.0049x over previous
#include <cuda_runtime.h>
#include <math.h>

// Problem constants (SUBDIVISIONS=7, BATCH=16)
#define BATCH    16
#define NV       163842        // total vertices (grid + 2 poles)
#define YXN      163840        // grid vertices (Y=640, X=256)
#define XDIM     256
#define NFACE    327680
#define NDIR     983040        // directed edges == 3*NFACE == sum(deg)
#define VPB      32            // vertices per block (512-thread blocks)

// Scratch (__device__ globals; no runtime allocation)
__device__ float4 g_vT[(size_t)NV * BATCH];  // positions, [vertex][batch], w=0
__device__ int    g_off[NV + 1];             // CSR offsets (edge-degree == face-degree)
__device__ int    g_cursor[NV];
__device__ int2   g_pairs[NDIR];             // per vertex slot: opposite edge (p,q), cyclic
__device__ int    g_ring[NDIR];              // ring-ordered neighbor ids per vertex
__device__ double g_acc;

// ---------------------------------------------------------------------------
// K0: CSR offsets from sorted edge_src; zero cursors + accumulator
// ---------------------------------------------------------------------------
__global__ void k_prep(const int* __restrict__ esrc) {
    int t = blockIdx.x * blockDim.x + threadIdx.x;
    if (t < NDIR) {
        int s = __ldg(&esrc[t]);
        if (t == 0) g_off[s] = 0;
        else if (__ldg(&esrc[t - 1]) != s) g_off[s] = t;
    }
    if (t < NV) g_cursor[t] = 0;
    if (t == 0) { g_acc = 0.0; g_off[NV] = NDIR; }
}

// ---------------------------------------------------------------------------
// K1: per face (a,b,c), deposit the opposite edge in cyclic order at each corner
// ---------------------------------------------------------------------------
__global__ void k_pairs(const int* __restrict__ faces) {
    int f = blockIdx.x * blockDim.x + threadIdx.x;
    if (f >= NFACE) return;
    int a = __ldg(&faces[3 * f]);
    int b = __ldg(&faces[3 * f + 1]);
    int c = __ldg(&faces[3 * f + 2]);
    int pa = atomicAdd(&g_cursor[a], 1); g_pairs[g_off[a] + pa] = make_int2(b, c);
    int pb = atomicAdd(&g_cursor[b], 1); g_pairs[g_off[b] + pb] = make_int2(c, a);
    int pc = atomicAdd(&g_cursor[c], 1); g_pairs[g_off[c] + pc] = make_int2(a, b);
}

// ---------------------------------------------------------------------------
// K2: chain (p,q) pairs into a deterministic ring order per vertex
// (start at min p; winding direction preserved so the cross-product sign
//  matches the reference's face-normal sum exactly)
// ---------------------------------------------------------------------------
__global__ void k_ring(void) {
    int i = blockIdx.x * blockDim.x + threadIdx.x;
    if (i >= NV) return;
    int s   = g_off[i];
    int cnt = g_off[i + 1] - s;      // 5 or 6
    int p[6], q[6];
#pragma unroll
    for (int k = 0; k < 6; k++) {
        int2 pr = (k < cnt) ? g_pairs[s + k] : make_int2(0x7fffffff, 0x7fffffff);
        p[k] = pr.x; q[k] = pr.y;
    }
    int cur = 0x7fffffff, nxt = 0;
#pragma unroll
    for (int k = 0; k < 6; k++) if (p[k] < cur) { cur = p[k]; nxt = q[k]; }
    g_ring[s] = cur;
    cur = nxt;
    for (int t = 1; t < cnt; t++) {
        g_ring[s + t] = cur;
        int nq = cur;
#pragma unroll
        for (int k = 0; k < 6; k++) if (p[k] == cur) nq = q[k];
        cur = nq;
    }
}

// ---------------------------------------------------------------------------
// K3: build transposed positions g_vT[vertex][batch]; block = 32 verts x 16 b.
// Pole vertices handled by block 0's first warp at the end.
// ---------------------------------------------------------------------------
__global__ void __launch_bounds__(512) k_build_v(const float* __restrict__ inp) {
    __shared__ float st[3][VPB][BATCH + 1];
    int tid = threadIdx.x;
    int i0  = blockIdx.x * VPB;
    // Stage: full 128B lines (32 consecutive floats per warp, fixed (b,c))
    {
        int lo = tid & 31;          // vertex offset
        int hv = tid >> 5;          // batch
        size_t base = (size_t)hv * 3 * YXN + (size_t)(i0 + lo);
#pragma unroll
        for (int c = 0; c < 3; c++)
            st[c][lo][hv] = __ldg(&inp[base + (size_t)c * YXN]);
    }
    __syncthreads();
    // Write: tid-ordered consecutive float4 (512B per warp, coalesced)
    {
        int hv2 = tid >> 4;         // local vertex
        int lo2 = tid & 15;         // batch
        g_vT[(size_t)(i0 + hv2) * BATCH + lo2] =
            make_float4(st[0][hv2][lo2], st[1][hv2][lo2], st[2][hv2][lo2], 0.f);
    }
    // Poles (fused): 2 poles x 16 batches by block 0's first warp
    if (blockIdx.x == 0 && tid < 32) {
        int b    = tid & 15;
        int pole = tid >> 4;
        const float* base = inp + (size_t)b * 3 * YXN;
        float sx = 0.f, sy = 0.f, sz = 0.f;
#pragma unroll
        for (int r = 0; r < 5; r++) {
            int idx = pole ? ((r * 128 + 127) * XDIM + (XDIM - 1))
                           : (r * 128 * XDIM);
            sx += __ldg(&base[idx]);
            sy += __ldg(&base[YXN + idx]);
            sz += __ldg(&base[2 * YXN + idx]);
        }
        g_vT[(size_t)(YXN + pole) * BATCH + b] =
            make_float4(sx * 0.2f, sy * 0.2f, sz * 0.2f, 0.f);
    }
}

// ---------------------------------------------------------------------------
// K4: fused loss. Block = 32 vertices x 16 batches; half-warp = 1 vertex.
// vn_i = sum of cross(v_t, v_{t+1}) over the ordered ring (exact identity
// with the reference's per-face cross(v1-v0, v2-v0) fan sum).
// ---------------------------------------------------------------------------
__global__ void __launch_bounds__(512)
k_main(const float* __restrict__ target) {
    __shared__ float st[9][VPB][BATCH + 1];
    int tid = threadIdx.x;
    int i0  = blockIdx.x * VPB;

    // Stage target tile: full 128B lines per (c, batch) row
    {
        int lo = tid & 31;          // vertex offset
        int hv = tid >> 5;          // batch
        int gi = i0 + lo;
        size_t base = (size_t)hv * 9 * NV + (size_t)gi;
#pragma unroll
        for (int c = 0; c < 9; c++)
            st[c][lo][hv] = (gi < NV) ? __ldg(&target[base + (size_t)c * NV]) : 0.f;
    }
    __syncthreads();

    int hv2 = tid >> 4;             // local vertex (0..31)
    int b   = tid & 15;             // batch
    int i   = i0 + hv2;
    float contrib = 0.f;

    if (i < NV) {
        int s   = __ldg(&g_off[i]);
        int cnt = __ldg(&g_off[i + 1]) - s;    // 5 or 6 (uniform per half-warp)

        float4 vi = g_vT[(size_t)i * BATCH + b];

        int idx[6];
#pragma unroll
        for (int t = 0; t < 6; t++)
            idx[t] = (t < cnt) ? __ldg(&g_ring[s + t]) : 0;

        // Gather neighbor positions: 16 consecutive float4 per half-warp
        float4 nb[6];
#pragma unroll
        for (int t = 0; t < 6; t++)
            nb[t] = g_vT[(size_t)idx[t] * BATCH + b];

        // Laplacian neighbor sum
        float nx = 0.f, ny = 0.f, nz = 0.f;
#pragma unroll
        for (int t = 0; t < 6; t++)
            if (t < cnt) { nx += nb[t].x; ny += nb[t].y; nz += nb[t].z; }

        // Vertex normal via ring cross sum (+ wrap)
        float vnx = 0.f, vny = 0.f, vnz = 0.f;
#pragma unroll
        for (int t = 0; t < 5; t++) {
            if (t + 1 < cnt) {
                vnx += nb[t].y * nb[t + 1].z - nb[t].z * nb[t + 1].y;
                vny += nb[t].z * nb[t + 1].x - nb[t].x * nb[t + 1].z;
                vnz += nb[t].x * nb[t + 1].y - nb[t].y * nb[t + 1].x;
            }
        }
        float4 last = (cnt == 6) ? nb[5] : nb[4];
        vnx += last.y * nb[0].z - last.z * nb[0].y;
        vny += last.z * nb[0].x - last.x * nb[0].z;
        vnz += last.x * nb[0].y - last.y * nb[0].x;

        float idg = 1.0f / (float)cnt;
        float lx = vi.x - nx * idg;
        float ly = vi.y - ny * idg;
        float lz = vi.z - nz * idg;

        float tvx = st[0][hv2][b], tvy = st[1][hv2][b], tvz = st[2][hv2][b];
        float tnx = st[3][hv2][b], tny = st[4][hv2][b], tnz = st[5][hv2][b];
        float tlx = st[6][hv2][b], tly = st[7][hv2][b], tlz = st[8][hv2][b];

        float dpx = vi.x - tvx, dpy = vi.y - tvy, dpz = vi.z - tvz;
        float pos_sse = dpx * dpx + dpy * dpy + dpz * dpz;

        float dlx = lx - tlx, dly = ly - tly, dlz = lz - tlz;
        float lap_sse = dlx * dlx + dly * dly + dlz * dlz;

        // cosine, replicating the reference's epsilon chain
        float nrm   = sqrtf(vnx * vnx + vny * vny + vnz * vnz);
        float inv_n = 1.0f / fmaxf(nrm, 1e-12f);
        float hx = vnx * inv_n, hy = vny * inv_n, hz = vnz * inv_n;
        float hn  = sqrtf(hx * hx + hy * hy + hz * hz);
        float tnn = sqrtf(tnx * tnx + tny * tny + tnz * tnz);
        float cosv = (hx * tnx + hy * tny + hz * tnz) / fmaxf(hn * tnn, 1e-8f);

        const float invP = 1.0f / ((float)BATCH * (float)NV * 3.0f);
        const float invN = 1.0f / ((float)BATCH * (float)NV);
        contrib = (pos_sse + lap_sse) * invP + (1.0f - cosv) * invN;
    }

    // Block reduce -> one double atomic per block
#pragma unroll
    for (int o = 16; o > 0; o >>= 1)
        contrib += __shfl_down_sync(0xffffffff, contrib, o);

    __shared__ float ws[16];
    int lane = threadIdx.x & 31;
    int w    = threadIdx.x >> 5;
    if (lane == 0) ws[w] = contrib;
    __syncthreads();
    if (w == 0) {
        float v = (lane < 16) ? ws[lane] : 0.f;
#pragma unroll
        for (int o = 8; o > 0; o >>= 1)
            v += __shfl_down_sync(0xffff, v, o);
        if (lane == 0) atomicAdd(&g_acc, (double)v);
    }
}

__global__ void k_final(float* __restrict__ out) {
    out[0] = (float)g_acc;
}

// ---------------------------------------------------------------------------
// inputs order: inputs, target, ico_faces, edge_src, edge_dst, degree
// ---------------------------------------------------------------------------
extern "C" void kernel_launch(void* const* d_in, const int* in_sizes, int n_in,
                              void* d_out, int out_size) {
    const float* inputs = (const float*)d_in[0];
    const float* target = (const float*)d_in[1];
    const int*   faces  = (const int*)  d_in[2];
    const int*   esrc   = (const int*)  d_in[3];

    const int TB = 256;

    k_prep <<<(NDIR + TB - 1) / TB, TB>>>(esrc);
    k_pairs<<<(NFACE + TB - 1) / TB, TB>>>(faces);
    k_ring <<<(NV + TB - 1) / TB, TB>>>();

    k_build_v<<<YXN / VPB, 512>>>(inputs);

    k_main<<<(NV + VPB - 1) / VPB, 512>>>(target);
    k_final<<<1, 1>>>((float*)d_out);
}